// round 2
// baseline (speedup 1.0000x reference)
#include <cuda_runtime.h>

// ---------------------------------------------------------------------------
// Problem constants
// ---------------------------------------------------------------------------
#define EDIM   1024
#define FFDIM  4096
#define BATCH  4
#define SEQ    2048
#define ROWS   (BATCH * SEQ)          // 8192
#define EPSV   1e-5f

// ---------------------------------------------------------------------------
// Scratch (static device globals: no allocation in kernel_launch)
// ---------------------------------------------------------------------------
__device__ float g_Q   [(size_t)ROWS * EDIM];
__device__ float g_K   [(size_t)ROWS * EDIM];
__device__ float g_V   [(size_t)ROWS * EDIM];
__device__ float g_S   [(size_t)BATCH * SEQ * SEQ];   // scores / probs (67 MB)
__device__ float g_attn[(size_t)ROWS * EDIM];
__device__ float g_tmp [(size_t)ROWS * EDIM];
__device__ float g_x   [(size_t)ROWS * EDIM];
__device__ float g_ff  [(size_t)ROWS * FFDIM];

// ---------------------------------------------------------------------------
// SGEMM: C[M,N] = A[M,K] * op(B) (+ bias) (+ relu)
//   TRANSB = false : B is [K,N] row-major        (NN)
//   TRANSB = true  : B is [N,K] row-major, use B^T (NT)
// Batched via gridDim.z with element strides sA/sB/sC.
// Requires: M % 128 == 0, N % 128 == 0, K % 8 == 0 (true for all our shapes).
// Tile: 128x128x8, 256 threads, 8x8 accumulator per thread.
// ---------------------------------------------------------------------------
template<bool TRANSB, bool RELU>
__global__ __launch_bounds__(256)
void sgemm_k(const float* __restrict__ A, const float* __restrict__ B,
             const float* __restrict__ bias, float* __restrict__ C,
             int M, int N, int K, size_t sA, size_t sB, size_t sC)
{
    __shared__ float As[8][128];
    __shared__ float Bs[8][128];

    const int tid = threadIdx.x;
    const int ty  = tid >> 4;        // 0..15  -> row group of 8
    const int tx  = tid & 15;        // 0..15  -> col group of 8

    const float* Ag = A + blockIdx.z * sA + (size_t)(blockIdx.y * 128) * K;
    const float* Bg = B + blockIdx.z * sB;
    float*       Cg = C + blockIdx.z * sC + (size_t)(blockIdx.y * 128) * N
                        + (size_t)(blockIdx.x * 128);

    const int lr = tid >> 1;         // 0..127 (row within tile for A / NT-B loads)
    const int lc = (tid & 1) * 4;    // 0 or 4 (k offset, float4 granularity)

    float acc[8][8];
    #pragma unroll
    for (int i = 0; i < 8; i++)
        #pragma unroll
        for (int j = 0; j < 8; j++) acc[i][j] = 0.f;

    for (int k0 = 0; k0 < K; k0 += 8) {
        // --- load A tile (128 rows x 8 k), store k-major for conflict-free LDS
        float4 av = *(const float4*)(Ag + (size_t)lr * K + (k0 + lc));
        As[lc + 0][lr] = av.x;
        As[lc + 1][lr] = av.y;
        As[lc + 2][lr] = av.z;
        As[lc + 3][lr] = av.w;

        // --- load B tile
        if (TRANSB) {
            // B[N,K]: tile rows are output columns
            float4 bv = *(const float4*)(Bg + (size_t)(blockIdx.x * 128 + lr) * K + (k0 + lc));
            Bs[lc + 0][lr] = bv.x;
            Bs[lc + 1][lr] = bv.y;
            Bs[lc + 2][lr] = bv.z;
            Bs[lc + 3][lr] = bv.w;
        } else {
            // B[K,N]: 8 rows of 128 floats
            const int brow = tid >> 5;        // 0..7
            const int bcol = (tid & 31) * 4;  // 0..124
            float4 bv = *(const float4*)(Bg + (size_t)(k0 + brow) * N
                                            + (size_t)(blockIdx.x * 128 + bcol));
            *(float4*)&Bs[brow][bcol] = bv;
        }
        __syncthreads();

        // --- compute
        #pragma unroll
        for (int k = 0; k < 8; k++) {
            float4 a0 = *(const float4*)&As[k][ty * 8];
            float4 a1 = *(const float4*)&As[k][ty * 8 + 4];
            float4 b0 = *(const float4*)&Bs[k][tx * 8];
            float4 b1 = *(const float4*)&Bs[k][tx * 8 + 4];
            float ar[8] = {a0.x, a0.y, a0.z, a0.w, a1.x, a1.y, a1.z, a1.w};
            float br[8] = {b0.x, b0.y, b0.z, b0.w, b1.x, b1.y, b1.z, b1.w};
            #pragma unroll
            for (int i = 0; i < 8; i++)
                #pragma unroll
                for (int j = 0; j < 8; j++)
                    acc[i][j] = fmaf(ar[i], br[j], acc[i][j]);
        }
        __syncthreads();
    }

    // --- epilogue: bias + optional relu, float4 stores
    float bb[8];
    #pragma unroll
    for (int j = 0; j < 8; j++) bb[j] = 0.f;
    if (bias != nullptr) {
        #pragma unroll
        for (int j = 0; j < 8; j++)
            bb[j] = bias[blockIdx.x * 128 + tx * 8 + j];
    }

    #pragma unroll
    for (int i = 0; i < 8; i++) {
        float* cp = Cg + (size_t)(ty * 8 + i) * N + tx * 8;
        float v[8];
        #pragma unroll
        for (int j = 0; j < 8; j++) {
            v[j] = acc[i][j] + bb[j];
            if (RELU) v[j] = fmaxf(v[j], 0.f);
        }
        *(float4*)(cp + 0) = make_float4(v[0], v[1], v[2], v[3]);
        *(float4*)(cp + 4) = make_float4(v[4], v[5], v[6], v[7]);
    }
}

// ---------------------------------------------------------------------------
// Row softmax over SEQ=2048 columns, in place. One block (256 threads) per row.
// 8 elements per thread live in registers: one global read + one write.
// ---------------------------------------------------------------------------
__global__ __launch_bounds__(256)
void softmax_k(float* __restrict__ S)
{
    float* p = S + (size_t)blockIdx.x * SEQ;
    const int tid = threadIdx.x;
    __shared__ float red[256];

    float r[8];
    float m = -1e30f;
    #pragma unroll
    for (int i = 0; i < 8; i++) {
        r[i] = p[tid + i * 256];
        m = fmaxf(m, r[i]);
    }
    red[tid] = m;
    __syncthreads();
    #pragma unroll
    for (int s = 128; s > 0; s >>= 1) {
        if (tid < s) red[tid] = fmaxf(red[tid], red[tid + s]);
        __syncthreads();
    }
    m = red[0];
    __syncthreads();

    float sum = 0.f;
    #pragma unroll
    for (int i = 0; i < 8; i++) {
        r[i] = __expf(r[i] - m);
        sum += r[i];
    }
    red[tid] = sum;
    __syncthreads();
    #pragma unroll
    for (int s = 128; s > 0; s >>= 1) {
        if (tid < s) red[tid] += red[tid + s];
        __syncthreads();
    }
    const float inv = 1.f / red[0];
    #pragma unroll
    for (int i = 0; i < 8; i++)
        p[tid + i * 256] = r[i] * inv;
}

// ---------------------------------------------------------------------------
// out = LayerNorm(a + b) * g + beta, rows of EDIM=1024. 256 threads/row.
// ---------------------------------------------------------------------------
__global__ __launch_bounds__(256)
void add_ln_k(const float* __restrict__ a, const float* __restrict__ b,
              const float* __restrict__ g, const float* __restrict__ beta,
              float* __restrict__ out)
{
    const size_t base = (size_t)blockIdx.x * EDIM;
    const int tid = threadIdx.x;
    __shared__ float r1[256];
    __shared__ float r2[256];

    float v[4];
    float s = 0.f, sq = 0.f;
    #pragma unroll
    for (int i = 0; i < 4; i++) {
        const int c = tid + i * 256;
        v[i] = a[base + c] + b[base + c];
        s  += v[i];
        sq += v[i] * v[i];
    }
    r1[tid] = s;
    r2[tid] = sq;
    __syncthreads();
    #pragma unroll
    for (int st = 128; st > 0; st >>= 1) {
        if (tid < st) { r1[tid] += r1[tid + st]; r2[tid] += r2[tid + st]; }
        __syncthreads();
    }
    const float mu  = r1[0] * (1.f / EDIM);
    const float var = r2[0] * (1.f / EDIM) - mu * mu;
    const float inv = rsqrtf(var + EPSV);
    #pragma unroll
    for (int i = 0; i < 4; i++) {
        const int c = tid + i * 256;
        out[base + c] = (v[i] - mu) * inv * g[c] + beta[c];
    }
}

// ---------------------------------------------------------------------------
// Launch sequence
// ---------------------------------------------------------------------------
extern "C" void kernel_launch(void* const* d_in, const int* in_sizes, int n_in,
                              void* d_out, int out_size)
{
    (void)in_sizes; (void)n_in; (void)out_size;

    const float* src = (const float*)d_in[0];
    const float* Wq  = (const float*)d_in[1];
    const float* bq  = (const float*)d_in[2];
    const float* Wk  = (const float*)d_in[3];
    const float* bk  = (const float*)d_in[4];
    const float* Wv  = (const float*)d_in[5];
    const float* bv  = (const float*)d_in[6];
    const float* Wo  = (const float*)d_in[7];
    const float* bo  = (const float*)d_in[8];
    const float* W1  = (const float*)d_in[9];
    const float* b1  = (const float*)d_in[10];
    const float* W2  = (const float*)d_in[11];
    const float* b2  = (const float*)d_in[12];
    const float* g1  = (const float*)d_in[13];
    const float* be1 = (const float*)d_in[14];
    const float* g2  = (const float*)d_in[15];
    const float* be2 = (const float*)d_in[16];
    float* out = (float*)d_out;

    float *Q, *K, *V, *S, *attn, *tmp, *x, *ff;
    cudaGetSymbolAddress((void**)&Q,    g_Q);
    cudaGetSymbolAddress((void**)&K,    g_K);
    cudaGetSymbolAddress((void**)&V,    g_V);
    cudaGetSymbolAddress((void**)&S,    g_S);
    cudaGetSymbolAddress((void**)&attn, g_attn);
    cudaGetSymbolAddress((void**)&tmp,  g_tmp);
    cudaGetSymbolAddress((void**)&x,    g_x);
    cudaGetSymbolAddress((void**)&ff,   g_ff);

    const dim3 blk(256);

    // 1-3. Q/K/V projections: [8192,1024] = src @ W[1024,1024] + b
    {
        dim3 grd(EDIM / 128, ROWS / 128, 1);
        sgemm_k<false, false><<<grd, blk>>>(src, Wq, bq, Q, ROWS, EDIM, EDIM, 0, 0, 0);
        sgemm_k<false, false><<<grd, blk>>>(src, Wk, bk, K, ROWS, EDIM, EDIM, 0, 0, 0);
        sgemm_k<false, false><<<grd, blk>>>(src, Wv, bv, V, ROWS, EDIM, EDIM, 0, 0, 0);
    }

    // 4. scores: per batch, S_b[2048,2048] = Q_b @ K_b^T   (NO 1/sqrt(d) scaling)
    {
        dim3 grd(SEQ / 128, SEQ / 128, BATCH);
        sgemm_k<true, false><<<grd, blk>>>(
            Q, K, nullptr, S, SEQ, SEQ, EDIM,
            (size_t)SEQ * EDIM, (size_t)SEQ * EDIM, (size_t)SEQ * SEQ);
    }

    // 5. row softmax over 8192 rows of 2048
    softmax_k<<<ROWS, blk>>>(S);

    // 6. attn: per batch, attn_b[2048,1024] = P_b @ V_b
    {
        dim3 grd(EDIM / 128, SEQ / 128, BATCH);
        sgemm_k<false, false><<<grd, blk>>>(
            S, V, nullptr, attn, SEQ, EDIM, SEQ,
            (size_t)SEQ * SEQ, (size_t)SEQ * EDIM, (size_t)SEQ * EDIM);
    }

    // 7. output projection: tmp = attn @ Wo + bo
    {
        dim3 grd(EDIM / 128, ROWS / 128, 1);
        sgemm_k<false, false><<<grd, blk>>>(attn, Wo, bo, tmp, ROWS, EDIM, EDIM, 0, 0, 0);
    }

    // 8. x = LN(src + tmp) * g1 + be1
    add_ln_k<<<ROWS, blk>>>(src, tmp, g1, be1, x);

    // 9. ff = relu(x @ W1 + b1)   [8192,4096]
    {
        dim3 grd(FFDIM / 128, ROWS / 128, 1);
        sgemm_k<false, true><<<grd, blk>>>(x, W1, b1, ff, ROWS, FFDIM, EDIM, 0, 0, 0);
    }

    // 10. tmp = ff @ W2 + b2      [8192,1024]
    {
        dim3 grd(EDIM / 128, ROWS / 128, 1);
        sgemm_k<false, false><<<grd, blk>>>(ff, W2, b2, tmp, ROWS, EDIM, FFDIM, 0, 0, 0);
    }

    // 11. out = LN(x + tmp) * g2 + be2
    add_ln_k<<<ROWS, blk>>>(x, tmp, g2, be2, out);
}

// round 5
// speedup vs baseline: 2.5924x; 2.5924x over previous
#include <cuda_runtime.h>
#include <cuda_bf16.h>
#include <cstdint>

// ===========================================================================
// Problem constants
// ===========================================================================
#define E_DIM  1024
#define FF_DIM 4096
#define NB     4
#define SEQ    2048
#define NROWS  (NB * SEQ)        // 8192
#define EPSV   1e-5f

// GEMM tiling: CTA 128x128, K-step 64, 256 threads (8 warps of 64x32)
#define BM 128
#define BN 128
#define BK 64
#define TILE_B   (128 * BK * 2)          // 16 KB per (tile,half)
#define STAGE_B  (4 * TILE_B)            // Ah, Al, Bh, Bl = 64 KB
#define SMEM_GEMM (2 * STAGE_B)          // double buffer = 128 KB

typedef __nv_bfloat16 bf;

// ===========================================================================
// Scratch
// ===========================================================================
static __device__ __align__(1024) unsigned char g_buf[671088640];

// ===========================================================================
// PTX helpers (all sm_80-era: legal under compute_100)
// ===========================================================================
__device__ __forceinline__ uint32_t smem_u32(const void* p) {
    uint32_t a;
    asm("{ .reg .u64 t; cvta.to.shared.u64 t, %1; cvt.u32.u64 %0, t; }" : "=r"(a) : "l"(p));
    return a;
}
#define CP16(s, g) \
    asm volatile("cp.async.cg.shared.global [%0], [%1], 16;" :: "r"(s), "l"(g) : "memory")
#define CP_COMMIT() asm volatile("cp.async.commit_group;" ::: "memory")
#define CP_WAIT0()  asm volatile("cp.async.wait_group 0;" ::: "memory")
#define CP_WAIT1()  asm volatile("cp.async.wait_group 1;" ::: "memory")

__device__ __forceinline__ void ldm4(uint32_t* r, uint32_t addr) {
    asm volatile("ldmatrix.sync.aligned.m8n8.x4.shared.b16 {%0,%1,%2,%3}, [%4];"
        : "=r"(r[0]), "=r"(r[1]), "=r"(r[2]), "=r"(r[3]) : "r"(addr));
}
__device__ __forceinline__ void mma16816(float* d, const uint32_t* a, const uint32_t* b) {
    asm volatile("mma.sync.aligned.m16n8k16.row.col.f32.bf16.bf16.f32 "
        "{%0,%1,%2,%3}, {%4,%5,%6,%7}, {%8,%9}, {%0,%1,%2,%3};"
        : "+f"(d[0]), "+f"(d[1]), "+f"(d[2]), "+f"(d[3])
        : "r"(a[0]), "r"(a[1]), "r"(a[2]), "r"(a[3]), "r"(b[0]), "r"(b[1]));
}

// smem tile: 128 rows x 64 bf16 (128 B/row), XOR-8 swizzle on 16B chunks
#define SWZ(r, kc) ((uint32_t)((r) * 128 + ((((kc) ^ ((r) & 7))) << 4)))

// ===========================================================================
// split helpers
// ===========================================================================
union BF2U { __nv_bfloat162 h; uint32_t u; };
__device__ __forceinline__ void split_pair(float a, float b, uint32_t& hp, uint32_t& lp)
{
    BF2U h; h.h = __floats2bfloat162_rn(a, b);
    BF2U l; l.h = __floats2bfloat162_rn(a - __low2float(h.h), b - __high2float(h.h));
    hp = h.u; lp = l.u;
}

// ===========================================================================
// HMMA GEMM: C[z][M,N] = A[z][M,K] @ B[z][N,K]^T  (A,B pre-split bf16 hi/lo)
// D accumulated fp32 via AhBh + AhBl + AlBh.
// ===========================================================================
template<bool SPLIT_OUT, bool RELU>
__global__ __launch_bounds__(256, 1)
void mma_gemm(const bf* __restrict__ Ah, const bf* __restrict__ Al,
              const bf* __restrict__ Bh, const bf* __restrict__ Bl,
              const float* __restrict__ bias, float* __restrict__ Cf,
              bf* __restrict__ Ch, bf* __restrict__ Cl,
              int N, int K, size_t sA, size_t sB, size_t sC)
{
    extern __shared__ __align__(1024) unsigned char smem[];
    const uint32_t sb0 = smem_u32(smem);

    const int tid  = threadIdx.x;
    const int lane = tid & 31;
    const int warp = tid >> 5;
    const int wm   = (warp >> 2) * 64;   // 0 / 64
    const int wn   = (warp & 3) * 32;    // 0..96
    const int m0   = blockIdx.y * BM;
    const int n0   = blockIdx.x * BN;
    const int z    = blockIdx.z;
    const int nk   = K / BK;

    const bf* pAh = Ah + (size_t)z * sA + (size_t)m0 * K;
    const bf* pAl = Al + (size_t)z * sA + (size_t)m0 * K;
    const bf* pBh = Bh + (size_t)z * sB + (size_t)n0 * K;
    const bf* pBl = Bl + (size_t)z * sB + (size_t)n0 * K;

    // ---- async tile loader: 4 tiles of [128 x 64] bf16 into stage s
    auto load_stage = [&](int s, int i) {
        const uint32_t base = sb0 + s * STAGE_B;
        const int k0 = i * BK;
        #pragma unroll
        for (int j = 0; j < 4; j++) {
            const int idx = tid + j * 256;
            const int r  = idx >> 3;
            const int kc = idx & 7;
            const uint32_t so = SWZ(r, kc);
            const size_t go = (size_t)r * K + k0 + kc * 8;
            CP16(base + so,              pAh + go);
            CP16(base + TILE_B + so,     pAl + go);
            CP16(base + 2 * TILE_B + so, pBh + go);
            CP16(base + 3 * TILE_B + so, pBl + go);
        }
    };

    float acc[4][4][4];
    #pragma unroll
    for (int m = 0; m < 4; m++)
        #pragma unroll
        for (int n = 0; n < 4; n++)
            #pragma unroll
            for (int q = 0; q < 4; q++) acc[m][n][q] = 0.f;

    load_stage(0, 0);
    CP_COMMIT();

    for (int i = 0; i < nk; i++) {
        const int s = i & 1;
        if (i + 1 < nk) { load_stage(s ^ 1, i + 1); CP_COMMIT(); CP_WAIT1(); }
        else            { CP_WAIT0(); }
        __syncthreads();

        const uint32_t Ahb = sb0 + s * STAGE_B;
        const uint32_t Alb = Ahb + TILE_B;
        const uint32_t Bhb = Ahb + 2 * TILE_B;
        const uint32_t Blb = Ahb + 3 * TILE_B;

        #pragma unroll
        for (int ks = 0; ks < 4; ks++) {
            const int lrow = lane & 15;
            const int kc   = ks * 2 + (lane >> 4);

            uint32_t ah[4][4], al[4][4];
            #pragma unroll
            for (int f = 0; f < 4; f++) {
                const int r = wm + f * 16 + lrow;
                ldm4(ah[f], Ahb + SWZ(r, kc));
                ldm4(al[f], Alb + SWZ(r, kc));
            }
            uint32_t bh[4][2], bl[4][2];
            #pragma unroll
            for (int g = 0; g < 2; g++) {
                const int r = wn + g * 16 + lrow;
                uint32_t t4[4], u4[4];
                ldm4(t4, Bhb + SWZ(r, kc));
                ldm4(u4, Blb + SWZ(r, kc));
                bh[g*2+0][0] = t4[0]; bh[g*2+0][1] = t4[2];
                bh[g*2+1][0] = t4[1]; bh[g*2+1][1] = t4[3];
                bl[g*2+0][0] = u4[0]; bl[g*2+0][1] = u4[2];
                bl[g*2+1][0] = u4[1]; bl[g*2+1][1] = u4[3];
            }
            #pragma unroll
            for (int m = 0; m < 4; m++)
                #pragma unroll
                for (int n = 0; n < 4; n++) {
                    mma16816(acc[m][n], ah[m], bh[n]);
                    mma16816(acc[m][n], ah[m], bl[n]);
                    mma16816(acc[m][n], al[m], bh[n]);
                }
        }
        __syncthreads();
    }

    // ---- epilogue
    const int qr = lane >> 2;          // 0..7
    const int qc = (lane & 3) * 2;     // 0,2,4,6
    const size_t zoff = (size_t)z * sC;

    #pragma unroll
    for (int m = 0; m < 4; m++) {
        #pragma unroll
        for (int n = 0; n < 4; n++) {
            const int row = m0 + wm + m * 16 + qr;
            const int col = n0 + wn + n * 8 + qc;
            float v0 = acc[m][n][0], v1 = acc[m][n][1];
            float v2 = acc[m][n][2], v3 = acc[m][n][3];
            if (bias) {
                const float b0 = __ldg(&bias[col]), b1 = __ldg(&bias[col + 1]);
                v0 += b0; v1 += b1; v2 += b0; v3 += b1;
            }
            if (RELU) {
                v0 = fmaxf(v0, 0.f); v1 = fmaxf(v1, 0.f);
                v2 = fmaxf(v2, 0.f); v3 = fmaxf(v3, 0.f);
            }
            const size_t o0 = zoff + (size_t)row * N + col;
            const size_t o1 = zoff + (size_t)(row + 8) * N + col;
            if (!SPLIT_OUT) {
                *(float2*)(Cf + o0) = make_float2(v0, v1);
                *(float2*)(Cf + o1) = make_float2(v2, v3);
            } else {
                uint32_t h0, l0, h1, l1;
                split_pair(v0, v1, h0, l0);
                split_pair(v2, v3, h1, l1);
                *(uint32_t*)(Ch + o0) = h0;
                *(uint32_t*)(Cl + o0) = l0;
                *(uint32_t*)(Ch + o1) = h1;
                *(uint32_t*)(Cl + o1) = l1;
            }
        }
    }
}

// ===========================================================================
// fp32 flat -> bf16 hi/lo
// ===========================================================================
__global__ __launch_bounds__(256)
void split_k(const float4* __restrict__ in, uint2* __restrict__ oh, uint2* __restrict__ ol, int n4)
{
    int i = blockIdx.x * 256 + threadIdx.x;
    if (i >= n4) return;
    float4 v = in[i];
    uint2 h, l;
    split_pair(v.x, v.y, h.x, l.x);
    split_pair(v.z, v.w, h.y, l.y);
    oh[i] = h; ol[i] = l;
}

// fp32 [z][R][C] -> transposed split [z][C][R]
__global__ __launch_bounds__(256)
void tsplit_k(const float* __restrict__ in, bf* __restrict__ oh, bf* __restrict__ ol, int R, int C)
{
    __shared__ float t[32][33];
    const size_t zo = (size_t)blockIdx.z * R * C;
    const int r0 = blockIdx.y * 32, c0 = blockIdx.x * 32;
    const int tx = threadIdx.x & 31, ty = threadIdx.x >> 5;
    #pragma unroll
    for (int i = 0; i < 4; i++)
        t[ty + i * 8][tx] = in[zo + (size_t)(r0 + ty + i * 8) * C + c0 + tx];
    __syncthreads();
    #pragma unroll
    for (int i = 0; i < 4; i++) {
        const int orow = c0 + ty + i * 8, oc = r0 + tx;
        float v = t[tx][ty + i * 8];
        bf h = __float2bfloat16(v);
        oh[zo + (size_t)orow * R + oc] = h;
        ol[zo + (size_t)orow * R + oc] = __float2bfloat16(v - __bfloat162float(h));
    }
}

// ===========================================================================
// row softmax (2048 cols) -> split bf16
// ===========================================================================
__global__ __launch_bounds__(256)
void softmax_k(const float* __restrict__ S, bf* __restrict__ ph, bf* __restrict__ pl)
{
    const size_t rb = (size_t)blockIdx.x * SEQ;
    const int tid = threadIdx.x;
    __shared__ float red[256];
    float4 a = *(const float4*)(S + rb + tid * 8);
    float4 b = *(const float4*)(S + rb + tid * 8 + 4);
    float r[8] = {a.x, a.y, a.z, a.w, b.x, b.y, b.z, b.w};
    float m = -1e30f;
    #pragma unroll
    for (int i = 0; i < 8; i++) m = fmaxf(m, r[i]);
    red[tid] = m; __syncthreads();
    #pragma unroll
    for (int s = 128; s > 0; s >>= 1) { if (tid < s) red[tid] = fmaxf(red[tid], red[tid + s]); __syncthreads(); }
    m = red[0]; __syncthreads();
    float sum = 0.f;
    #pragma unroll
    for (int i = 0; i < 8; i++) { r[i] = __expf(r[i] - m); sum += r[i]; }
    red[tid] = sum; __syncthreads();
    #pragma unroll
    for (int s = 128; s > 0; s >>= 1) { if (tid < s) red[tid] += red[tid + s]; __syncthreads(); }
    const float inv = 1.f / red[0];
    uint32_t hp[4], lp[4];
    #pragma unroll
    for (int q = 0; q < 4; q++) split_pair(r[2*q] * inv, r[2*q+1] * inv, hp[q], lp[q]);
    *(uint4*)(ph + rb + tid * 8) = make_uint4(hp[0], hp[1], hp[2], hp[3]);
    *(uint4*)(pl + rb + tid * 8) = make_uint4(lp[0], lp[1], lp[2], lp[3]);
}

// ===========================================================================
// out = LN(a+b)*g + beta  (+ optional split emit)
// ===========================================================================
template<bool WSPLIT>
__global__ __launch_bounds__(256)
void add_ln_k(const float* __restrict__ a, const float* __restrict__ b,
              const float* __restrict__ g, const float* __restrict__ beta,
              float* __restrict__ out, bf* __restrict__ oh, bf* __restrict__ ol)
{
    const size_t base = (size_t)blockIdx.x * E_DIM;
    const int tid = threadIdx.x, c = tid * 4;
    __shared__ float r1[256], r2[256];
    float4 va = *(const float4*)(a + base + c);
    float4 vb = *(const float4*)(b + base + c);
    float v[4] = {va.x + vb.x, va.y + vb.y, va.z + vb.z, va.w + vb.w};
    float s = 0.f, sq = 0.f;
    #pragma unroll
    for (int i = 0; i < 4; i++) { s += v[i]; sq += v[i] * v[i]; }
    r1[tid] = s; r2[tid] = sq; __syncthreads();
    #pragma unroll
    for (int st = 128; st > 0; st >>= 1) {
        if (tid < st) { r1[tid] += r1[tid + st]; r2[tid] += r2[tid + st]; }
        __syncthreads();
    }
    const float mu = r1[0] * (1.f / E_DIM);
    const float inv = rsqrtf(r2[0] * (1.f / E_DIM) - mu * mu + EPSV);
    float4 g4 = *(const float4*)(g + c);
    float4 b4 = *(const float4*)(beta + c);
    float o[4] = {(v[0]-mu)*inv*g4.x + b4.x, (v[1]-mu)*inv*g4.y + b4.y,
                  (v[2]-mu)*inv*g4.z + b4.z, (v[3]-mu)*inv*g4.w + b4.w};
    *(float4*)(out + base + c) = make_float4(o[0], o[1], o[2], o[3]);
    if (WSPLIT) {
        uint2 h, l;
        split_pair(o[0], o[1], h.x, l.x);
        split_pair(o[2], o[3], h.y, l.y);
        *(uint2*)(oh + base + c) = h;
        *(uint2*)(ol + base + c) = l;
    }
}

// ===========================================================================
// Host
// ===========================================================================
extern "C" void kernel_launch(void* const* d_in, const int* in_sizes, int n_in,
                              void* d_out, int out_size)
{
    (void)in_sizes; (void)n_in; (void)out_size;
    const float* src = (const float*)d_in[0];
    const float* Wq = (const float*)d_in[1];  const float* bq = (const float*)d_in[2];
    const float* Wk = (const float*)d_in[3];  const float* bk = (const float*)d_in[4];
    const float* Wv = (const float*)d_in[5];  const float* bv = (const float*)d_in[6];
    const float* Wo = (const float*)d_in[7];  const float* bo = (const float*)d_in[8];
    const float* W1 = (const float*)d_in[9];  const float* b1 = (const float*)d_in[10];
    const float* W2 = (const float*)d_in[11]; const float* b2 = (const float*)d_in[12];
    const float* g1 = (const float*)d_in[13]; const float* be1 = (const float*)d_in[14];
    const float* g2 = (const float*)d_in[15]; const float* be2 = (const float*)d_in[16];
    float* out = (float*)d_out;

    unsigned char* base = nullptr;
    cudaGetSymbolAddress((void**)&base, g_buf);
    size_t cur = 0;
    auto carve = [&](size_t bytes) { unsigned char* p = base + cur; cur += (bytes + 255) & ~(size_t)255; return p; };

    const size_t RE = (size_t)NROWS * E_DIM, RFF = (size_t)NROWS * FF_DIM;
    const size_t SS = (size_t)NB * SEQ * SEQ;
    const size_t WEE = (size_t)E_DIM * E_DIM, WEF = (size_t)E_DIM * FF_DIM;

    float* S_  = (float*)carve(SS * 4);
    float* Vf  = (float*)carve(RE * 4);
    float* tmp = (float*)carve(RE * 4);
    float* x   = (float*)carve(RE * 4);
    bf* srch = (bf*)carve(RE*2);  bf* srcl = (bf*)carve(RE*2);
    bf* Qh = (bf*)carve(RE*2);    bf* Ql = (bf*)carve(RE*2);
    bf* Kh = (bf*)carve(RE*2);    bf* Kl = (bf*)carve(RE*2);
    bf* Vth = (bf*)carve(RE*2);   bf* Vtl = (bf*)carve(RE*2);
    bf* Ph = (bf*)carve(SS*2);    bf* Pl = (bf*)carve(SS*2);
    bf* ath = (bf*)carve(RE*2);   bf* atl = (bf*)carve(RE*2);
    bf* xh = (bf*)carve(RE*2);    bf* xl = (bf*)carve(RE*2);
    bf* ffh = (bf*)carve(RFF*2);  bf* ffl = (bf*)carve(RFF*2);
    bf* Wqh = (bf*)carve(WEE*2);  bf* Wql = (bf*)carve(WEE*2);
    bf* Wkh = (bf*)carve(WEE*2);  bf* Wkl = (bf*)carve(WEE*2);
    bf* Wvh = (bf*)carve(WEE*2);  bf* Wvl = (bf*)carve(WEE*2);
    bf* Woh = (bf*)carve(WEE*2);  bf* Wol = (bf*)carve(WEE*2);
    bf* W1h = (bf*)carve(WEF*2);  bf* W1l = (bf*)carve(WEF*2);
    bf* W2h = (bf*)carve(WEF*2);  bf* W2l = (bf*)carve(WEF*2);

    cudaFuncSetAttribute(mma_gemm<false,false>, cudaFuncAttributeMaxDynamicSharedMemorySize, SMEM_GEMM);
    cudaFuncSetAttribute(mma_gemm<true, false>, cudaFuncAttributeMaxDynamicSharedMemorySize, SMEM_GEMM);
    cudaFuncSetAttribute(mma_gemm<true, true >, cudaFuncAttributeMaxDynamicSharedMemorySize, SMEM_GEMM);

    const dim3 b256(256);
    // weight transposes ([in,out] -> [out,in] split) + src split
    tsplit_k<<<dim3(E_DIM/32,  E_DIM/32, 1), b256>>>(Wq, Wqh, Wql, E_DIM, E_DIM);
    tsplit_k<<<dim3(E_DIM/32,  E_DIM/32, 1), b256>>>(Wk, Wkh, Wkl, E_DIM, E_DIM);
    tsplit_k<<<dim3(E_DIM/32,  E_DIM/32, 1), b256>>>(Wv, Wvh, Wvl, E_DIM, E_DIM);
    tsplit_k<<<dim3(E_DIM/32,  E_DIM/32, 1), b256>>>(Wo, Woh, Wol, E_DIM, E_DIM);
    tsplit_k<<<dim3(FF_DIM/32, E_DIM/32, 1), b256>>>(W1, W1h, W1l, E_DIM, FF_DIM);
    tsplit_k<<<dim3(E_DIM/32,  FF_DIM/32,1), b256>>>(W2, W2h, W2l, FF_DIM, E_DIM);
    split_k<<<(int)(RE/4/256), b256>>>((const float4*)src, (uint2*)srch, (uint2*)srcl, (int)(RE/4));

    // QKV projections (Q,K split-out; V fp32 for transpose)
    {
        dim3 g(E_DIM/BN, NROWS/BM, 1);
        mma_gemm<true, false><<<g, b256, SMEM_GEMM>>>(srch, srcl, Wqh, Wql, bq, nullptr, Qh, Ql, E_DIM, E_DIM, 0, 0, 0);
        mma_gemm<true, false><<<g, b256, SMEM_GEMM>>>(srch, srcl, Wkh, Wkl, bk, nullptr, Kh, Kl, E_DIM, E_DIM, 0, 0, 0);
        mma_gemm<false,false><<<g, b256, SMEM_GEMM>>>(srch, srcl, Wvh, Wvl, bv, Vf, nullptr, nullptr, E_DIM, E_DIM, 0, 0, 0);
    }
    // V transpose per batch: [S,E] -> [E,S] split
    tsplit_k<<<dim3(E_DIM/32, SEQ/32, NB), b256>>>(Vf, Vth, Vtl, SEQ, E_DIM);

    // scores: S_b = Q_b @ K_b^T (fp32 out)
    mma_gemm<false,false><<<dim3(SEQ/BN, SEQ/BM, NB), b256, SMEM_GEMM>>>(
        Qh, Ql, Kh, Kl, nullptr, S_, nullptr, nullptr, SEQ, E_DIM,
        (size_t)SEQ*E_DIM, (size_t)SEQ*E_DIM, (size_t)SEQ*SEQ);

    softmax_k<<<NROWS, b256>>>(S_, Ph, Pl);

    // attn: P_b @ V_b  (B = Vt[E,S])
    mma_gemm<true, false><<<dim3(E_DIM/BN, SEQ/BM, NB), b256, SMEM_GEMM>>>(
        Ph, Pl, Vth, Vtl, nullptr, nullptr, ath, atl, E_DIM, SEQ,
        (size_t)SEQ*SEQ, (size_t)E_DIM*SEQ, (size_t)SEQ*E_DIM);

    // O projection
    mma_gemm<false,false><<<dim3(E_DIM/BN, NROWS/BM, 1), b256, SMEM_GEMM>>>(
        ath, atl, Woh, Wol, bo, tmp, nullptr, nullptr, E_DIM, E_DIM, 0, 0, 0);

    add_ln_k<true><<<NROWS, b256>>>(src, tmp, g1, be1, x, xh, xl);

    // FFN1 (relu, split out)
    mma_gemm<true, true><<<dim3(FF_DIM/BN, NROWS/BM, 1), b256, SMEM_GEMM>>>(
        xh, xl, W1h, W1l, b1, nullptr, ffh, ffl, FF_DIM, E_DIM, 0, 0, 0);

    // FFN2
    mma_gemm<false,false><<<dim3(E_DIM/BN, NROWS/BM, 1), b256, SMEM_GEMM>>>(
        ffh, ffl, W2h, W2l, b2, tmp, nullptr, nullptr, E_DIM, FF_DIM, 0, 0, 0);

    add_ln_k<false><<<NROWS, b256>>>(x, tmp, g2, be2, out, nullptr, nullptr);
}

// round 7
// speedup vs baseline: 2.6439x; 1.0199x over previous
#include <cuda_runtime.h>
#include <cuda_bf16.h>
#include <cstdint>

// ===========================================================================
// Problem constants
// ===========================================================================
#define E_DIM  1024
#define FF_DIM 4096
#define NB     4
#define SEQ    2048
#define NROWS  (NB * SEQ)        // 8192
#define EPSV   1e-5f

// GEMM tiling: CTA 128x256, K-step 64, 256 threads (8 warps of 64x64)
#define BM 128
#define BN 256
#define BK 64
#define TILE_A   (128 * BK * 2)          // 16 KB  (A hi or lo)
#define TILE_BB  (256 * BK * 2)          // 32 KB  (B hi or lo)
#define STAGE_B  (2 * TILE_A + 2 * TILE_BB)   // 96 KB
#define SMEM_GEMM (2 * STAGE_B)          // double buffer = 192 KB

typedef __nv_bfloat16 bf;

// ===========================================================================
// Scratch
// ===========================================================================
static __device__ __align__(1024) unsigned char g_buf[671088640];

// ===========================================================================
// PTX helpers (all sm_80-era: legal under compute_100)
// ===========================================================================
__device__ __forceinline__ uint32_t smem_u32(const void* p) {
    uint32_t a;
    asm("{ .reg .u64 t; cvta.to.shared.u64 t, %1; cvt.u32.u64 %0, t; }" : "=r"(a) : "l"(p));
    return a;
}
#define CP16(s, g) \
    asm volatile("cp.async.cg.shared.global [%0], [%1], 16;" :: "r"(s), "l"(g) : "memory")
#define CP_COMMIT() asm volatile("cp.async.commit_group;" ::: "memory")
#define CP_WAIT0()  asm volatile("cp.async.wait_group 0;" ::: "memory")
#define CP_WAIT1()  asm volatile("cp.async.wait_group 1;" ::: "memory")

__device__ __forceinline__ void ldm4(uint32_t* r, uint32_t addr) {
    asm volatile("ldmatrix.sync.aligned.m8n8.x4.shared.b16 {%0,%1,%2,%3}, [%4];"
        : "=r"(r[0]), "=r"(r[1]), "=r"(r[2]), "=r"(r[3]) : "r"(addr));
}
__device__ __forceinline__ void mma16816(float* d, const uint32_t* a, const uint32_t* b) {
    asm volatile("mma.sync.aligned.m16n8k16.row.col.f32.bf16.bf16.f32 "
        "{%0,%1,%2,%3}, {%4,%5,%6,%7}, {%8,%9}, {%0,%1,%2,%3};"
        : "+f"(d[0]), "+f"(d[1]), "+f"(d[2]), "+f"(d[3])
        : "r"(a[0]), "r"(a[1]), "r"(a[2]), "r"(a[3]), "r"(b[0]), "r"(b[1]));
}

// smem tile row: 64 bf16 = 128 B; XOR-8 swizzle on 16B chunks
#define SWZ(r, kc) ((uint32_t)((r) * 128 + ((((kc) ^ ((r) & 7))) << 4)))

// ===========================================================================
// split helpers
// ===========================================================================
union BF2U { __nv_bfloat162 h; uint32_t u; };
__device__ __forceinline__ void split_pair(float a, float b, uint32_t& hp, uint32_t& lp)
{
    BF2U h; h.h = __floats2bfloat162_rn(a, b);
    BF2U l; l.h = __floats2bfloat162_rn(a - __low2float(h.h), b - __high2float(h.h));
    hp = h.u; lp = l.u;
}

// ===========================================================================
// HMMA GEMM: C[z][M,N] = A[z][M,K] @ B[z][N,K]^T  (A,B pre-split bf16 hi/lo)
// D accumulated fp32 via AhBh + AhBl + AlBh.
// CTA 128x256, 8 warps of 64x64.
// ===========================================================================
template<bool SPLIT_OUT, bool RELU>
__global__ __launch_bounds__(256, 1)
void mma_gemm(const bf* __restrict__ Ah, const bf* __restrict__ Al,
              const bf* __restrict__ Bh, const bf* __restrict__ Bl,
              const float* __restrict__ bias, float* __restrict__ Cf,
              bf* __restrict__ Ch, bf* __restrict__ Cl,
              int N, int K, size_t sA, size_t sB, size_t sC)
{
    extern __shared__ __align__(1024) unsigned char smem[];
    const uint32_t sb0 = smem_u32(smem);

    const int tid  = threadIdx.x;
    const int lane = tid & 31;
    const int warp = tid >> 5;
    const int wm   = (warp >> 2) * 64;   // 0 / 64
    const int wn   = (warp & 3) * 64;    // 0..192
    const int m0   = blockIdx.y * BM;
    const int n0   = blockIdx.x * BN;
    const int z    = blockIdx.z;
    const int nk   = K / BK;

    const bf* pAh = Ah + (size_t)z * sA + (size_t)m0 * K;
    const bf* pAl = Al + (size_t)z * sA + (size_t)m0 * K;
    const bf* pBh = Bh + (size_t)z * sB + (size_t)n0 * K;
    const bf* pBl = Bl + (size_t)z * sB + (size_t)n0 * K;

    // ---- async tile loader: A(128x64) hi/lo + B(256x64) hi/lo into stage s
    auto load_stage = [&](int s, int i) {
        const uint32_t base = sb0 + s * STAGE_B;
        const int k0 = i * BK;
        #pragma unroll
        for (int j = 0; j < 4; j++) {                 // A: 1024 chunks
            const int idx = tid + j * 256;
            const int r  = idx >> 3;
            const int kc = idx & 7;
            const uint32_t so = SWZ(r, kc);
            const size_t go = (size_t)r * K + k0 + kc * 8;
            CP16(base + so,          pAh + go);
            CP16(base + TILE_A + so, pAl + go);
        }
        #pragma unroll
        for (int j = 0; j < 8; j++) {                 // B: 2048 chunks
            const int idx = tid + j * 256;
            const int r  = idx >> 3;
            const int kc = idx & 7;
            const uint32_t so = SWZ(r, kc);
            const size_t go = (size_t)r * K + k0 + kc * 8;
            CP16(base + 2 * TILE_A + so,           pBh + go);
            CP16(base + 2 * TILE_A + TILE_BB + so, pBl + go);
        }
    };

    float acc[4][8][4];
    #pragma unroll
    for (int m = 0; m < 4; m++)
        #pragma unroll
        for (int n = 0; n < 8; n++)
            #pragma unroll
            for (int q = 0; q < 4; q++) acc[m][n][q] = 0.f;

    load_stage(0, 0);
    CP_COMMIT();

    for (int i = 0; i < nk; i++) {
        const int s = i & 1;
        if (i + 1 < nk) { load_stage(s ^ 1, i + 1); CP_COMMIT(); CP_WAIT1(); }
        else            { CP_WAIT0(); }
        __syncthreads();

        const uint32_t Ahb = sb0 + s * STAGE_B;
        const uint32_t Alb = Ahb + TILE_A;
        const uint32_t Bhb = Ahb + 2 * TILE_A;
        const uint32_t Blb = Ahb + 2 * TILE_A + TILE_BB;

        #pragma unroll
        for (int ks = 0; ks < 4; ks++) {
            const int lrow = lane & 15;
            const int kc   = ks * 2 + (lane >> 4);

            uint32_t ah[4][4], al[4][4];
            #pragma unroll
            for (int f = 0; f < 4; f++) {
                const int r = wm + f * 16 + lrow;
                ldm4(ah[f], Ahb + SWZ(r, kc));
                ldm4(al[f], Alb + SWZ(r, kc));
            }
            // B in two halves of 32 cols to bound register pressure
            #pragma unroll
            for (int half = 0; half < 2; half++) {
                uint32_t bh[4][2], bl[4][2];
                #pragma unroll
                for (int g = 0; g < 2; g++) {
                    const int r = wn + (half * 2 + g) * 16 + lrow;
                    uint32_t t4[4], u4[4];
                    ldm4(t4, Bhb + SWZ(r, kc));
                    ldm4(u4, Blb + SWZ(r, kc));
                    bh[g*2+0][0] = t4[0]; bh[g*2+0][1] = t4[2];
                    bh[g*2+1][0] = t4[1]; bh[g*2+1][1] = t4[3];
                    bl[g*2+0][0] = u4[0]; bl[g*2+0][1] = u4[2];
                    bl[g*2+1][0] = u4[1]; bl[g*2+1][1] = u4[3];
                }
                #pragma unroll
                for (int m = 0; m < 4; m++)
                    #pragma unroll
                    for (int nn = 0; nn < 4; nn++) {
                        float* a = acc[m][half * 4 + nn];
                        mma16816(a, ah[m], bh[nn]);
                        mma16816(a, ah[m], bl[nn]);
                        mma16816(a, al[m], bh[nn]);
                    }
            }
        }
        __syncthreads();
    }

    // ---- epilogue
    const int qr = lane >> 2;          // 0..7
    const int qc = (lane & 3) * 2;     // 0,2,4,6
    const size_t zoff = (size_t)z * sC;

    #pragma unroll
    for (int m = 0; m < 4; m++) {
        #pragma unroll
        for (int n = 0; n < 8; n++) {
            const int row = m0 + wm + m * 16 + qr;
            const int col = n0 + wn + n * 8 + qc;
            float v0 = acc[m][n][0], v1 = acc[m][n][1];
            float v2 = acc[m][n][2], v3 = acc[m][n][3];
            if (bias) {
                const float b0 = __ldg(&bias[col]), b1 = __ldg(&bias[col + 1]);
                v0 += b0; v1 += b1; v2 += b0; v3 += b1;
            }
            if (RELU) {
                v0 = fmaxf(v0, 0.f); v1 = fmaxf(v1, 0.f);
                v2 = fmaxf(v2, 0.f); v3 = fmaxf(v3, 0.f);
            }
            const size_t o0 = zoff + (size_t)row * N + col;
            const size_t o1 = zoff + (size_t)(row + 8) * N + col;
            if (!SPLIT_OUT) {
                *(float2*)(Cf + o0) = make_float2(v0, v1);
                *(float2*)(Cf + o1) = make_float2(v2, v3);
            } else {
                uint32_t h0, l0, h1, l1;
                split_pair(v0, v1, h0, l0);
                split_pair(v2, v3, h1, l1);
                *(uint32_t*)(Ch + o0) = h0;
                *(uint32_t*)(Cl + o0) = l0;
                *(uint32_t*)(Ch + o1) = h1;
                *(uint32_t*)(Cl + o1) = l1;
            }
        }
    }
}

// ===========================================================================
// fp32 flat -> bf16 hi/lo
// ===========================================================================
__global__ __launch_bounds__(256)
void split_k(const float4* __restrict__ in, uint2* __restrict__ oh, uint2* __restrict__ ol, int n4)
{
    int i = blockIdx.x * 256 + threadIdx.x;
    if (i >= n4) return;
    float4 v = in[i];
    uint2 h, l;
    split_pair(v.x, v.y, h.x, l.x);
    split_pair(v.z, v.w, h.y, l.y);
    oh[i] = h; ol[i] = l;
}

// fp32 [z][R][C] -> transposed split [z][C][R]
__global__ __launch_bounds__(256)
void tsplit_k(const float* __restrict__ in, bf* __restrict__ oh, bf* __restrict__ ol, int R, int C)
{
    __shared__ float t[32][33];
    const size_t zo = (size_t)blockIdx.z * R * C;
    const int r0 = blockIdx.y * 32, c0 = blockIdx.x * 32;
    const int tx = threadIdx.x & 31, ty = threadIdx.x >> 5;
    #pragma unroll
    for (int i = 0; i < 4; i++)
        t[ty + i * 8][tx] = in[zo + (size_t)(r0 + ty + i * 8) * C + c0 + tx];
    __syncthreads();
    #pragma unroll
    for (int i = 0; i < 4; i++) {
        const int orow = c0 + ty + i * 8, oc = r0 + tx;
        float v = t[tx][ty + i * 8];
        bf h = __float2bfloat16(v);
        oh[zo + (size_t)orow * R + oc] = h;
        ol[zo + (size_t)orow * R + oc] = __float2bfloat16(v - __bfloat162float(h));
    }
}

// ===========================================================================
// row softmax (2048 cols) -> split bf16
// ===========================================================================
__global__ __launch_bounds__(256)
void softmax_k(const float* __restrict__ S, bf* __restrict__ ph, bf* __restrict__ pl)
{
    const size_t rb = (size_t)blockIdx.x * SEQ;
    const int tid = threadIdx.x;
    __shared__ float red[256];
    float4 a = *(const float4*)(S + rb + tid * 8);
    float4 b = *(const float4*)(S + rb + tid * 8 + 4);
    float r[8] = {a.x, a.y, a.z, a.w, b.x, b.y, b.z, b.w};
    float m = -1e30f;
    #pragma unroll
    for (int i = 0; i < 8; i++) m = fmaxf(m, r[i]);
    red[tid] = m; __syncthreads();
    #pragma unroll
    for (int s = 128; s > 0; s >>= 1) { if (tid < s) red[tid] = fmaxf(red[tid], red[tid + s]); __syncthreads(); }
    m = red[0]; __syncthreads();
    float sum = 0.f;
    #pragma unroll
    for (int i = 0; i < 8; i++) { r[i] = __expf(r[i] - m); sum += r[i]; }
    red[tid] = sum; __syncthreads();
    #pragma unroll
    for (int s = 128; s > 0; s >>= 1) { if (tid < s) red[tid] += red[tid + s]; __syncthreads(); }
    const float inv = 1.f / red[0];
    uint32_t hp[4], lp[4];
    #pragma unroll
    for (int q = 0; q < 4; q++) split_pair(r[2*q] * inv, r[2*q+1] * inv, hp[q], lp[q]);
    *(uint4*)(ph + rb + tid * 8) = make_uint4(hp[0], hp[1], hp[2], hp[3]);
    *(uint4*)(pl + rb + tid * 8) = make_uint4(lp[0], lp[1], lp[2], lp[3]);
}

// ===========================================================================
// out = LN(a+b)*g + beta  (+ optional split emit)
// ===========================================================================
template<bool WSPLIT>
__global__ __launch_bounds__(256)
void add_ln_k(const float* __restrict__ a, const float* __restrict__ b,
              const float* __restrict__ g, const float* __restrict__ beta,
              float* __restrict__ out, bf* __restrict__ oh, bf* __restrict__ ol)
{
    const size_t base = (size_t)blockIdx.x * E_DIM;
    const int tid = threadIdx.x, c = tid * 4;
    __shared__ float r1[256], r2[256];
    float4 va = *(const float4*)(a + base + c);
    float4 vb = *(const float4*)(b + base + c);
    float v[4] = {va.x + vb.x, va.y + vb.y, va.z + vb.z, va.w + vb.w};
    float s = 0.f, sq = 0.f;
    #pragma unroll
    for (int i = 0; i < 4; i++) { s += v[i]; sq += v[i] * v[i]; }
    r1[tid] = s; r2[tid] = sq; __syncthreads();
    #pragma unroll
    for (int st = 128; st > 0; st >>= 1) {
        if (tid < st) { r1[tid] += r1[tid + st]; r2[tid] += r2[tid + st]; }
        __syncthreads();
    }
    const float mu = r1[0] * (1.f / E_DIM);
    const float inv = rsqrtf(r2[0] * (1.f / E_DIM) - mu * mu + EPSV);
    float4 g4 = *(const float4*)(g + c);
    float4 b4 = *(const float4*)(beta + c);
    float o[4] = {(v[0]-mu)*inv*g4.x + b4.x, (v[1]-mu)*inv*g4.y + b4.y,
                  (v[2]-mu)*inv*g4.z + b4.z, (v[3]-mu)*inv*g4.w + b4.w};
    *(float4*)(out + base + c) = make_float4(o[0], o[1], o[2], o[3]);
    if (WSPLIT) {
        uint2 h, l;
        split_pair(o[0], o[1], h.x, l.x);
        split_pair(o[2], o[3], h.y, l.y);
        *(uint2*)(oh + base + c) = h;
        *(uint2*)(ol + base + c) = l;
    }
}

// ===========================================================================
// Host
// ===========================================================================
extern "C" void kernel_launch(void* const* d_in, const int* in_sizes, int n_in,
                              void* d_out, int out_size)
{
    (void)in_sizes; (void)n_in; (void)out_size;
    const float* src = (const float*)d_in[0];
    const float* Wq = (const float*)d_in[1];  const float* bq = (const float*)d_in[2];
    const float* Wk = (const float*)d_in[3];  const float* bk = (const float*)d_in[4];
    const float* Wv = (const float*)d_in[5];  const float* bv = (const float*)d_in[6];
    const float* Wo = (const float*)d_in[7];  const float* bo = (const float*)d_in[8];
    const float* W1 = (const float*)d_in[9];  const float* b1 = (const float*)d_in[10];
    const float* W2 = (const float*)d_in[11]; const float* b2 = (const float*)d_in[12];
    const float* g1 = (const float*)d_in[13]; const float* be1 = (const float*)d_in[14];
    const float* g2 = (const float*)d_in[15]; const float* be2 = (const float*)d_in[16];
    float* out = (float*)d_out;

    unsigned char* base = nullptr;
    cudaGetSymbolAddress((void**)&base, g_buf);
    size_t cur = 0;
    auto carve = [&](size_t bytes) { unsigned char* p = base + cur; cur += (bytes + 255) & ~(size_t)255; return p; };

    const size_t RE = (size_t)NROWS * E_DIM, RFF = (size_t)NROWS * FF_DIM;
    const size_t SS = (size_t)NB * SEQ * SEQ;
    const size_t WEE = (size_t)E_DIM * E_DIM, WEF = (size_t)E_DIM * FF_DIM;

    float* S_  = (float*)carve(SS * 4);
    float* Vf  = (float*)carve(RE * 4);
    float* tmp = (float*)carve(RE * 4);
    float* x   = (float*)carve(RE * 4);
    bf* srch = (bf*)carve(RE*2);  bf* srcl = (bf*)carve(RE*2);
    bf* Qh = (bf*)carve(RE*2);    bf* Ql = (bf*)carve(RE*2);
    bf* Kh = (bf*)carve(RE*2);    bf* Kl = (bf*)carve(RE*2);
    bf* Vth = (bf*)carve(RE*2);   bf* Vtl = (bf*)carve(RE*2);
    bf* Ph = (bf*)carve(SS*2);    bf* Pl = (bf*)carve(SS*2);
    bf* ath = (bf*)carve(RE*2);   bf* atl = (bf*)carve(RE*2);
    bf* xh = (bf*)carve(RE*2);    bf* xl = (bf*)carve(RE*2);
    bf* ffh = (bf*)carve(RFF*2);  bf* ffl = (bf*)carve(RFF*2);
    bf* Wqh = (bf*)carve(WEE*2);  bf* Wql = (bf*)carve(WEE*2);
    bf* Wkh = (bf*)carve(WEE*2);  bf* Wkl = (bf*)carve(WEE*2);
    bf* Wvh = (bf*)carve(WEE*2);  bf* Wvl = (bf*)carve(WEE*2);
    bf* Woh = (bf*)carve(WEE*2);  bf* Wol = (bf*)carve(WEE*2);
    bf* W1h = (bf*)carve(WEF*2);  bf* W1l = (bf*)carve(WEF*2);
    bf* W2h = (bf*)carve(WEF*2);  bf* W2l = (bf*)carve(WEF*2);

    cudaFuncSetAttribute(mma_gemm<false,false>, cudaFuncAttributeMaxDynamicSharedMemorySize, SMEM_GEMM);
    cudaFuncSetAttribute(mma_gemm<true, false>, cudaFuncAttributeMaxDynamicSharedMemorySize, SMEM_GEMM);
    cudaFuncSetAttribute(mma_gemm<true, true >, cudaFuncAttributeMaxDynamicSharedMemorySize, SMEM_GEMM);

    const dim3 b256(256);
    // weight transposes ([in,out] -> [out,in] split) + src split
    tsplit_k<<<dim3(E_DIM/32,  E_DIM/32, 1), b256>>>(Wq, Wqh, Wql, E_DIM, E_DIM);
    tsplit_k<<<dim3(E_DIM/32,  E_DIM/32, 1), b256>>>(Wk, Wkh, Wkl, E_DIM, E_DIM);
    tsplit_k<<<dim3(E_DIM/32,  E_DIM/32, 1), b256>>>(Wv, Wvh, Wvl, E_DIM, E_DIM);
    tsplit_k<<<dim3(E_DIM/32,  E_DIM/32, 1), b256>>>(Wo, Woh, Wol, E_DIM, E_DIM);
    tsplit_k<<<dim3(FF_DIM/32, E_DIM/32, 1), b256>>>(W1, W1h, W1l, E_DIM, FF_DIM);
    tsplit_k<<<dim3(E_DIM/32,  FF_DIM/32,1), b256>>>(W2, W2h, W2l, FF_DIM, E_DIM);
    split_k<<<(int)(RE/4/256), b256>>>((const float4*)src, (uint2*)srch, (uint2*)srcl, (int)(RE/4));

    // QKV projections (Q,K split-out; V fp32 for transpose)
    {
        dim3 g(E_DIM/BN, NROWS/BM, 1);
        mma_gemm<true, false><<<g, b256, SMEM_GEMM>>>(srch, srcl, Wqh, Wql, bq, nullptr, Qh, Ql, E_DIM, E_DIM, 0, 0, 0);
        mma_gemm<true, false><<<g, b256, SMEM_GEMM>>>(srch, srcl, Wkh, Wkl, bk, nullptr, Kh, Kl, E_DIM, E_DIM, 0, 0, 0);
        mma_gemm<false,false><<<g, b256, SMEM_GEMM>>>(srch, srcl, Wvh, Wvl, bv, Vf, nullptr, nullptr, E_DIM, E_DIM, 0, 0, 0);
    }
    // V transpose per batch: [S,E] -> [E,S] split
    tsplit_k<<<dim3(E_DIM/32, SEQ/32, NB), b256>>>(Vf, Vth, Vtl, SEQ, E_DIM);

    // scores: S_b = Q_b @ K_b^T (fp32 out)
    mma_gemm<false,false><<<dim3(SEQ/BN, SEQ/BM, NB), b256, SMEM_GEMM>>>(
        Qh, Ql, Kh, Kl, nullptr, S_, nullptr, nullptr, SEQ, E_DIM,
        (size_t)SEQ*E_DIM, (size_t)SEQ*E_DIM, (size_t)SEQ*SEQ);

    softmax_k<<<NROWS, b256>>>(S_, Ph, Pl);

    // attn: P_b @ V_b  (B = Vt[E,S])
    mma_gemm<true, false><<<dim3(E_DIM/BN, SEQ/BM, NB), b256, SMEM_GEMM>>>(
        Ph, Pl, Vth, Vtl, nullptr, nullptr, ath, atl, E_DIM, SEQ,
        (size_t)SEQ*SEQ, (size_t)E_DIM*SEQ, (size_t)SEQ*E_DIM);

    // O projection
    mma_gemm<false,false><<<dim3(E_DIM/BN, NROWS/BM, 1), b256, SMEM_GEMM>>>(
        ath, atl, Woh, Wol, bo, tmp, nullptr, nullptr, E_DIM, E_DIM, 0, 0, 0);

    add_ln_k<true><<<NROWS, b256>>>(src, tmp, g1, be1, x, xh, xl);

    // FFN1 (relu, split out)
    mma_gemm<true, true><<<dim3(FF_DIM/BN, NROWS/BM, 1), b256, SMEM_GEMM>>>(
        xh, xl, W1h, W1l, b1, nullptr, ffh, ffl, FF_DIM, E_DIM, 0, 0, 0);

    // FFN2
    mma_gemm<false,false><<<dim3(E_DIM/BN, NROWS/BM, 1), b256, SMEM_GEMM>>>(
        ffh, ffl, W2h, W2l, b2, tmp, nullptr, nullptr, E_DIM, FF_DIM, 0, 0, 0);

    add_ln_k<false><<<NROWS, b256>>>(x, tmp, g2, be2, out, nullptr, nullptr);
}

// round 11
// speedup vs baseline: 2.6737x; 1.0113x over previous
#include <cuda_runtime.h>
#include <cuda_bf16.h>
#include <cstdint>

// ===========================================================================
// Problem constants
// ===========================================================================
#define E_DIM  1024
#define FF_DIM 4096
#define NB     4
#define SEQ    2048
#define NROWS  (NB * SEQ)        // 8192
#define EPSV   1e-5f

// GEMM tiling: CTA 128x256, K-step 64, 256 threads (8 warps of 64x64)
#define BM 128
#define BN 256
#define BK 64
#define TILE_A   (128 * BK * 2)          // 16 KB  (A hi or lo)
#define TILE_BB  (256 * BK * 2)          // 32 KB  (B hi or lo)
#define STAGE_B  (2 * TILE_A + 2 * TILE_BB)   // 96 KB
#define SMEM_GEMM (2 * STAGE_B)          // double buffer = 192 KB

typedef __nv_bfloat16 bf;

// ===========================================================================
// Scratch
// ===========================================================================
static __device__ __align__(1024) unsigned char g_buf[671088640];

// ===========================================================================
// PTX helpers (all sm_80-era: legal under compute_100)
// ===========================================================================
__device__ __forceinline__ uint32_t smem_u32(const void* p) {
    uint32_t a;
    asm("{ .reg .u64 t; cvta.to.shared.u64 t, %1; cvt.u32.u64 %0, t; }" : "=r"(a) : "l"(p));
    return a;
}
#define CP16(s, g) \
    asm volatile("cp.async.cg.shared.global [%0], [%1], 16;" :: "r"(s), "l"(g) : "memory")
#define CP_COMMIT() asm volatile("cp.async.commit_group;" ::: "memory")
#define CP_WAIT0()  asm volatile("cp.async.wait_group 0;" ::: "memory")

__device__ __forceinline__ void ldm4(uint32_t* r, uint32_t addr) {
    asm volatile("ldmatrix.sync.aligned.m8n8.x4.shared.b16 {%0,%1,%2,%3}, [%4];"
        : "=r"(r[0]), "=r"(r[1]), "=r"(r[2]), "=r"(r[3]) : "r"(addr));
}
__device__ __forceinline__ void mma16816(float* d, const uint32_t* a, const uint32_t* b) {
    asm volatile("mma.sync.aligned.m16n8k16.row.col.f32.bf16.bf16.f32 "
        "{%0,%1,%2,%3}, {%4,%5,%6,%7}, {%8,%9}, {%0,%1,%2,%3};"
        : "+f"(d[0]), "+f"(d[1]), "+f"(d[2]), "+f"(d[3])
        : "r"(a[0]), "r"(a[1]), "r"(a[2]), "r"(a[3]), "r"(b[0]), "r"(b[1]));
}

// smem tile row: 64 bf16 = 128 B; XOR-8 swizzle on 16B chunks
#define SWZ(r, kc) ((uint32_t)((r) * 128 + ((((kc) ^ ((r) & 7))) << 4)))

// ===========================================================================
// split helpers
// ===========================================================================
union BF2U { __nv_bfloat162 h; uint32_t u; };
__device__ __forceinline__ void split_pair(float a, float b, uint32_t& hp, uint32_t& lp)
{
    BF2U h; h.h = __floats2bfloat162_rn(a, b);
    BF2U l; l.h = __floats2bfloat162_rn(a - __low2float(h.h), b - __high2float(h.h));
    hp = h.u; lp = l.u;
}

// ===========================================================================
// GEMM core: C[M,N] tile = A[M,K] @ B[N,K]^T  (pre-split bf16 hi/lo)
// fp32 accum via AhBh + AhBl + AlBh. CTA 128x256, 8 warps of 64x64.
// Single __syncthreads per K-iteration: [wait][sync][load next][compute].
// ===========================================================================
template<bool SPLIT_OUT, bool RELU>
__device__ __forceinline__ void gemm_core(
    const bf* pAh, const bf* pAl, const bf* pBh, const bf* pBl,
    const float* bias, float* Cf, bf* Ch, bf* Cl,
    int N, int K, int m0, int n0, uint32_t sb0)
{
    const int tid  = threadIdx.x;
    const int lane = tid & 31;
    const int warp = tid >> 5;
    const int wm   = (warp >> 2) * 64;   // 0 / 64
    const int wn   = (warp & 3) * 64;    // 0..192
    const int nk   = K / BK;

    auto load_stage = [&](int s, int i) {
        const uint32_t base = sb0 + s * STAGE_B;
        const int k0 = i * BK;
        #pragma unroll
        for (int j = 0; j < 4; j++) {                 // A: 1024 16B chunks
            const int idx = tid + j * 256;
            const int r  = idx >> 3;
            const int kc = idx & 7;
            const uint32_t so = SWZ(r, kc);
            const size_t go = (size_t)r * K + k0 + kc * 8;
            CP16(base + so,          pAh + go);
            CP16(base + TILE_A + so, pAl + go);
        }
        #pragma unroll
        for (int j = 0; j < 8; j++) {                 // B: 2048 16B chunks
            const int idx = tid + j * 256;
            const int r  = idx >> 3;
            const int kc = idx & 7;
            const uint32_t so = SWZ(r, kc);
            const size_t go = (size_t)r * K + k0 + kc * 8;
            CP16(base + 2 * TILE_A + so,           pBh + go);
            CP16(base + 2 * TILE_A + TILE_BB + so, pBl + go);
        }
    };

    float acc[4][8][4];
    #pragma unroll
    for (int m = 0; m < 4; m++)
        #pragma unroll
        for (int n = 0; n < 8; n++)
            #pragma unroll
            for (int q = 0; q < 4; q++) acc[m][n][q] = 0.f;

    load_stage(0, 0);
    CP_COMMIT();

    for (int i = 0; i < nk; i++) {
        const int s = i & 1;
        // wait for stage s loads; ONE barrier per iteration. The barrier also
        // proves every warp finished computing stage s^1 (program order), so
        // overwriting s^1 below is safe.
        CP_WAIT0();
        __syncthreads();
        if (i + 1 < nk) { load_stage(s ^ 1, i + 1); CP_COMMIT(); }

        const uint32_t Ahb = sb0 + s * STAGE_B;
        const uint32_t Alb = Ahb + TILE_A;
        const uint32_t Bhb = Ahb + 2 * TILE_A;
        const uint32_t Blb = Ahb + 2 * TILE_A + TILE_BB;

        #pragma unroll
        for (int ks = 0; ks < 4; ks++) {
            const int lrow = lane & 15;
            const int kc   = ks * 2 + (lane >> 4);

            uint32_t ah[4][4], al[4][4];
            #pragma unroll
            for (int f = 0; f < 4; f++) {
                const int r = wm + f * 16 + lrow;
                ldm4(ah[f], Ahb + SWZ(r, kc));
                ldm4(al[f], Alb + SWZ(r, kc));
            }
            #pragma unroll
            for (int half = 0; half < 2; half++) {
                uint32_t bh[4][2], bl[4][2];
                #pragma unroll
                for (int g = 0; g < 2; g++) {
                    const int r = wn + (half * 2 + g) * 16 + lrow;
                    uint32_t t4[4], u4[4];
                    ldm4(t4, Bhb + SWZ(r, kc));
                    ldm4(u4, Blb + SWZ(r, kc));
                    bh[g*2+0][0] = t4[0]; bh[g*2+0][1] = t4[2];
                    bh[g*2+1][0] = t4[1]; bh[g*2+1][1] = t4[3];
                    bl[g*2+0][0] = u4[0]; bl[g*2+0][1] = u4[2];
                    bl[g*2+1][0] = u4[1]; bl[g*2+1][1] = u4[3];
                }
                #pragma unroll
                for (int m = 0; m < 4; m++)
                    #pragma unroll
                    for (int nn = 0; nn < 4; nn++) {
                        float* a = acc[m][half * 4 + nn];
                        mma16816(a, ah[m], bh[nn]);
                        mma16816(a, ah[m], bl[nn]);
                        mma16816(a, al[m], bh[nn]);
                    }
            }
        }
    }

    // ---- epilogue (register-only inputs; no barrier needed)
    const int qr = lane >> 2;
    const int qc = (lane & 3) * 2;

    #pragma unroll
    for (int m = 0; m < 4; m++) {
        #pragma unroll
        for (int n = 0; n < 8; n++) {
            const int row = m0 + wm + m * 16 + qr;
            const int col = n0 + wn + n * 8 + qc;
            float v0 = acc[m][n][0], v1 = acc[m][n][1];
            float v2 = acc[m][n][2], v3 = acc[m][n][3];
            if (bias) {
                const float b0 = __ldg(&bias[col]), b1 = __ldg(&bias[col + 1]);
                v0 += b0; v1 += b1; v2 += b0; v3 += b1;
            }
            if (RELU) {
                v0 = fmaxf(v0, 0.f); v1 = fmaxf(v1, 0.f);
                v2 = fmaxf(v2, 0.f); v3 = fmaxf(v3, 0.f);
            }
            const size_t o0 = (size_t)row * N + col;
            const size_t o1 = (size_t)(row + 8) * N + col;
            if (!SPLIT_OUT) {
                *(float2*)(Cf + o0) = make_float2(v0, v1);
                *(float2*)(Cf + o1) = make_float2(v2, v3);
            } else {
                uint32_t h0, l0, h1, l1;
                split_pair(v0, v1, h0, l0);
                split_pair(v2, v3, h1, l1);
                *(uint32_t*)(Ch + o0) = h0;
                *(uint32_t*)(Cl + o0) = l0;
                *(uint32_t*)(Ch + o1) = h1;
                *(uint32_t*)(Cl + o1) = l1;
            }
        }
    }
}

// Generic batched GEMM kernel
template<bool SPLIT_OUT, bool RELU>
__global__ __launch_bounds__(256, 1)
void mma_gemm(const bf* __restrict__ Ah, const bf* __restrict__ Al,
              const bf* __restrict__ Bh, const bf* __restrict__ Bl,
              const float* __restrict__ bias, float* __restrict__ Cf,
              bf* __restrict__ Ch, bf* __restrict__ Cl,
              int N, int K, size_t sA, size_t sB, size_t sC)
{
    extern __shared__ __align__(1024) unsigned char smem[];
    const uint32_t sb0 = smem_u32(smem);
    const int m0 = blockIdx.y * BM;
    const int n0 = blockIdx.x * BN;
    const int z  = blockIdx.z;
    gemm_core<SPLIT_OUT, RELU>(
        Ah + (size_t)z * sA + (size_t)m0 * K,
        Al + (size_t)z * sA + (size_t)m0 * K,
        Bh + (size_t)z * sB + (size_t)n0 * K,
        Bl + (size_t)z * sB + (size_t)n0 * K,
        bias,
        Cf ? Cf + (size_t)z * sC : nullptr,
        Ch ? Ch + (size_t)z * sC : nullptr,
        Cl ? Cl + (size_t)z * sC : nullptr,
        N, K, m0, n0, sb0);
}

// Fused QKV: blockIdx.z selects {Q,K,V} weight/bias/output; all split-out.
__global__ __launch_bounds__(256, 1)
void qkv_gemm(const bf* __restrict__ Ah, const bf* __restrict__ Al,
              const bf* __restrict__ Wqh, const bf* __restrict__ Wql,
              const bf* __restrict__ Wkh, const bf* __restrict__ Wkl,
              const bf* __restrict__ Wvh, const bf* __restrict__ Wvl,
              const float* __restrict__ bq, const float* __restrict__ bk,
              const float* __restrict__ bv,
              bf* __restrict__ Qh, bf* __restrict__ Ql,
              bf* __restrict__ Kh, bf* __restrict__ Kl,
              bf* __restrict__ Vh, bf* __restrict__ Vl)
{
    extern __shared__ __align__(1024) unsigned char smem[];
    const uint32_t sb0 = smem_u32(smem);
    const int m0 = blockIdx.y * BM;
    const int n0 = blockIdx.x * BN;
    const int z  = blockIdx.z;

    const bf* Bh; const bf* Bl; const float* bias; bf* Ch; bf* Cl;
    if (z == 0)      { Bh = Wqh; Bl = Wql; bias = bq; Ch = Qh; Cl = Ql; }
    else if (z == 1) { Bh = Wkh; Bl = Wkl; bias = bk; Ch = Kh; Cl = Kl; }
    else             { Bh = Wvh; Bl = Wvl; bias = bv; Ch = Vh; Cl = Vl; }

    gemm_core<true, false>(
        Ah + (size_t)m0 * E_DIM, Al + (size_t)m0 * E_DIM,
        Bh + (size_t)n0 * E_DIM, Bl + (size_t)n0 * E_DIM,
        bias, nullptr, Ch, Cl, E_DIM, E_DIM, m0, n0, sb0);
}

// ===========================================================================
// fp32 flat -> bf16 hi/lo
// ===========================================================================
__global__ __launch_bounds__(256)
void split_k(const float4* __restrict__ in, uint2* __restrict__ oh, uint2* __restrict__ ol, int n4)
{
    int i = blockIdx.x * 256 + threadIdx.x;
    if (i >= n4) return;
    float4 v = in[i];
    uint2 h, l;
    split_pair(v.x, v.y, h.x, l.x);
    split_pair(v.z, v.w, h.y, l.y);
    oh[i] = h; ol[i] = l;
}

// fp32 [z][R][C] -> transposed split [z][C][R]  (weights)
__global__ __launch_bounds__(256)
void tsplit_k(const float* __restrict__ in, bf* __restrict__ oh, bf* __restrict__ ol, int R, int C)
{
    __shared__ float t[32][33];
    const size_t zo = (size_t)blockIdx.z * R * C;
    const int r0 = blockIdx.y * 32, c0 = blockIdx.x * 32;
    const int tx = threadIdx.x & 31, ty = threadIdx.x >> 5;
    #pragma unroll
    for (int i = 0; i < 4; i++)
        t[ty + i * 8][tx] = in[zo + (size_t)(r0 + ty + i * 8) * C + c0 + tx];
    __syncthreads();
    #pragma unroll
    for (int i = 0; i < 4; i++) {
        const int orow = c0 + ty + i * 8, oc = r0 + tx;
        float v = t[tx][ty + i * 8];
        bf h = __float2bfloat16(v);
        oh[zo + (size_t)orow * R + oc] = h;
        ol[zo + (size_t)orow * R + oc] = __float2bfloat16(v - __bfloat162float(h));
    }
}

// bf16 pair [z][R][C] -> transposed [z][C][R]  (V hi/lo; split is elementwise
// so transpose-of-split == split-of-transpose)
__global__ __launch_bounds__(256)
void t_bf_k(const bf* __restrict__ ih, const bf* __restrict__ il,
            bf* __restrict__ oh, bf* __restrict__ ol, int R, int C)
{
    __shared__ bf th[32][33];
    __shared__ bf tl[32][33];
    const size_t zo = (size_t)blockIdx.z * R * C;
    const int r0 = blockIdx.y * 32, c0 = blockIdx.x * 32;
    const int tx = threadIdx.x & 31, ty = threadIdx.x >> 5;
    #pragma unroll
    for (int i = 0; i < 4; i++) {
        const size_t gi = zo + (size_t)(r0 + ty + i * 8) * C + c0 + tx;
        th[ty + i * 8][tx] = ih[gi];
        tl[ty + i * 8][tx] = il[gi];
    }
    __syncthreads();
    #pragma unroll
    for (int i = 0; i < 4; i++) {
        const int orow = c0 + ty + i * 8, oc = r0 + tx;
        const size_t go = zo + (size_t)orow * R + oc;
        oh[go] = th[tx][ty + i * 8];
        ol[go] = tl[tx][ty + i * 8];
    }
}

// ===========================================================================
// row softmax (2048 cols) -> split bf16
// ===========================================================================
__global__ __launch_bounds__(256)
void softmax_k(const float* __restrict__ S, bf* __restrict__ ph, bf* __restrict__ pl)
{
    const size_t rb = (size_t)blockIdx.x * SEQ;
    const int tid = threadIdx.x;
    __shared__ float red[256];
    float4 a = *(const float4*)(S + rb + tid * 8);
    float4 b = *(const float4*)(S + rb + tid * 8 + 4);
    float r[8] = {a.x, a.y, a.z, a.w, b.x, b.y, b.z, b.w};
    float m = -1e30f;
    #pragma unroll
    for (int i = 0; i < 8; i++) m = fmaxf(m, r[i]);
    red[tid] = m; __syncthreads();
    #pragma unroll
    for (int s = 128; s > 0; s >>= 1) { if (tid < s) red[tid] = fmaxf(red[tid], red[tid + s]); __syncthreads(); }
    m = red[0]; __syncthreads();
    float sum = 0.f;
    #pragma unroll
    for (int i = 0; i < 8; i++) { r[i] = __expf(r[i] - m); sum += r[i]; }
    red[tid] = sum; __syncthreads();
    #pragma unroll
    for (int s = 128; s > 0; s >>= 1) { if (tid < s) red[tid] += red[tid + s]; __syncthreads(); }
    const float inv = 1.f / red[0];
    uint32_t hp[4], lp[4];
    #pragma unroll
    for (int q = 0; q < 4; q++) split_pair(r[2*q] * inv, r[2*q+1] * inv, hp[q], lp[q]);
    *(uint4*)(ph + rb + tid * 8) = make_uint4(hp[0], hp[1], hp[2], hp[3]);
    *(uint4*)(pl + rb + tid * 8) = make_uint4(lp[0], lp[1], lp[2], lp[3]);
}

// ===========================================================================
// out = LN(a+b)*g + beta  (+ optional split emit)
// ===========================================================================
template<bool WSPLIT>
__global__ __launch_bounds__(256)
void add_ln_k(const float* __restrict__ a, const float* __restrict__ b,
              const float* __restrict__ g, const float* __restrict__ beta,
              float* __restrict__ out, bf* __restrict__ oh, bf* __restrict__ ol)
{
    const size_t base = (size_t)blockIdx.x * E_DIM;
    const int tid = threadIdx.x, c = tid * 4;
    __shared__ float r1[256], r2[256];
    float4 va = *(const float4*)(a + base + c);
    float4 vb = *(const float4*)(b + base + c);
    float v[4] = {va.x + vb.x, va.y + vb.y, va.z + vb.z, va.w + vb.w};
    float s = 0.f, sq = 0.f;
    #pragma unroll
    for (int i = 0; i < 4; i++) { s += v[i]; sq += v[i] * v[i]; }
    r1[tid] = s; r2[tid] = sq; __syncthreads();
    #pragma unroll
    for (int st = 128; st > 0; st >>= 1) {
        if (tid < st) { r1[tid] += r1[tid + st]; r2[tid] += r2[tid + st]; }
        __syncthreads();
    }
    const float mu = r1[0] * (1.f / E_DIM);
    const float inv = rsqrtf(r2[0] * (1.f / E_DIM) - mu * mu + EPSV);
    float4 g4 = *(const float4*)(g + c);
    float4 b4 = *(const float4*)(beta + c);
    float o[4] = {(v[0]-mu)*inv*g4.x + b4.x, (v[1]-mu)*inv*g4.y + b4.y,
                  (v[2]-mu)*inv*g4.z + b4.z, (v[3]-mu)*inv*g4.w + b4.w};
    *(float4*)(out + base + c) = make_float4(o[0], o[1], o[2], o[3]);
    if (WSPLIT) {
        uint2 h, l;
        split_pair(o[0], o[1], h.x, l.x);
        split_pair(o[2], o[3], h.y, l.y);
        *(uint2*)(oh + base + c) = h;
        *(uint2*)(ol + base + c) = l;
    }
}

// ===========================================================================
// Host
// ===========================================================================
extern "C" void kernel_launch(void* const* d_in, const int* in_sizes, int n_in,
                              void* d_out, int out_size)
{
    (void)in_sizes; (void)n_in; (void)out_size;
    const float* src = (const float*)d_in[0];
    const float* Wq = (const float*)d_in[1];  const float* bq = (const float*)d_in[2];
    const float* Wk = (const float*)d_in[3];  const float* bk = (const float*)d_in[4];
    const float* Wv = (const float*)d_in[5];  const float* bv = (const float*)d_in[6];
    const float* Wo = (const float*)d_in[7];  const float* bo = (const float*)d_in[8];
    const float* W1 = (const float*)d_in[9];  const float* b1 = (const float*)d_in[10];
    const float* W2 = (const float*)d_in[11]; const float* b2 = (const float*)d_in[12];
    const float* g1 = (const float*)d_in[13]; const float* be1 = (const float*)d_in[14];
    const float* g2 = (const float*)d_in[15]; const float* be2 = (const float*)d_in[16];
    float* out = (float*)d_out;

    unsigned char* base = nullptr;
    cudaGetSymbolAddress((void**)&base, g_buf);
    size_t cur = 0;
    auto carve = [&](size_t bytes) { unsigned char* p = base + cur; cur += (bytes + 255) & ~(size_t)255; return p; };

    const size_t RE = (size_t)NROWS * E_DIM, RFF = (size_t)NROWS * FF_DIM;
    const size_t SS = (size_t)NB * SEQ * SEQ;
    const size_t WEE = (size_t)E_DIM * E_DIM, WEF = (size_t)E_DIM * FF_DIM;

    float* S_  = (float*)carve(SS * 4);
    float* tmp = (float*)carve(RE * 4);
    float* x   = (float*)carve(RE * 4);
    bf* srch = (bf*)carve(RE*2);  bf* srcl = (bf*)carve(RE*2);
    bf* Qh = (bf*)carve(RE*2);    bf* Ql = (bf*)carve(RE*2);
    bf* Kh = (bf*)carve(RE*2);    bf* Kl = (bf*)carve(RE*2);
    bf* Vh = (bf*)carve(RE*2);    bf* Vl = (bf*)carve(RE*2);
    bf* Vth = (bf*)carve(RE*2);   bf* Vtl = (bf*)carve(RE*2);
    bf* Ph = (bf*)carve(SS*2);    bf* Pl = (bf*)carve(SS*2);
    bf* ath = (bf*)carve(RE*2);   bf* atl = (bf*)carve(RE*2);
    bf* xh = (bf*)carve(RE*2);    bf* xl = (bf*)carve(RE*2);
    bf* ffh = (bf*)carve(RFF*2);  bf* ffl = (bf*)carve(RFF*2);
    bf* Wqh = (bf*)carve(WEE*2);  bf* Wql = (bf*)carve(WEE*2);
    bf* Wkh = (bf*)carve(WEE*2);  bf* Wkl = (bf*)carve(WEE*2);
    bf* Wvh = (bf*)carve(WEE*2);  bf* Wvl = (bf*)carve(WEE*2);
    bf* Woh = (bf*)carve(WEE*2);  bf* Wol = (bf*)carve(WEE*2);
    bf* W1h = (bf*)carve(WEF*2);  bf* W1l = (bf*)carve(WEF*2);
    bf* W2h = (bf*)carve(WEF*2);  bf* W2l = (bf*)carve(WEF*2);

    cudaFuncSetAttribute(mma_gemm<false,false>, cudaFuncAttributeMaxDynamicSharedMemorySize, SMEM_GEMM);
    cudaFuncSetAttribute(mma_gemm<true, false>, cudaFuncAttributeMaxDynamicSharedMemorySize, SMEM_GEMM);
    cudaFuncSetAttribute(mma_gemm<true, true >, cudaFuncAttributeMaxDynamicSharedMemorySize, SMEM_GEMM);
    cudaFuncSetAttribute(qkv_gemm,              cudaFuncAttributeMaxDynamicSharedMemorySize, SMEM_GEMM);

    const dim3 b256(256);
    // weight transposes ([in,out] -> [out,in] split) + src split
    tsplit_k<<<dim3(E_DIM/32,  E_DIM/32, 1), b256>>>(Wq, Wqh, Wql, E_DIM, E_DIM);
    tsplit_k<<<dim3(E_DIM/32,  E_DIM/32, 1), b256>>>(Wk, Wkh, Wkl, E_DIM, E_DIM);
    tsplit_k<<<dim3(E_DIM/32,  E_DIM/32, 1), b256>>>(Wv, Wvh, Wvl, E_DIM, E_DIM);
    tsplit_k<<<dim3(E_DIM/32,  E_DIM/32, 1), b256>>>(Wo, Woh, Wol, E_DIM, E_DIM);
    tsplit_k<<<dim3(FF_DIM/32, E_DIM/32, 1), b256>>>(W1, W1h, W1l, E_DIM, FF_DIM);
    tsplit_k<<<dim3(E_DIM/32,  FF_DIM/32,1), b256>>>(W2, W2h, W2l, FF_DIM, E_DIM);
    split_k<<<(int)(RE/4/256), b256>>>((const float4*)src, (uint2*)srch, (uint2*)srcl, (int)(RE/4));

    // Fused QKV projections (single launch, z selects Q/K/V)
    qkv_gemm<<<dim3(E_DIM/BN, NROWS/BM, 3), b256, SMEM_GEMM>>>(
        srch, srcl, Wqh, Wql, Wkh, Wkl, Wvh, Wvl, bq, bk, bv,
        Qh, Ql, Kh, Kl, Vh, Vl);

    // V transpose per batch: [S,E] -> [E,S], hi/lo in one pass
    t_bf_k<<<dim3(E_DIM/32, SEQ/32, NB), b256>>>(Vh, Vl, Vth, Vtl, SEQ, E_DIM);

    // scores: S_b = Q_b @ K_b^T (fp32 out)
    mma_gemm<false,false><<<dim3(SEQ/BN, SEQ/BM, NB), b256, SMEM_GEMM>>>(
        Qh, Ql, Kh, Kl, nullptr, S_, nullptr, nullptr, SEQ, E_DIM,
        (size_t)SEQ*E_DIM, (size_t)SEQ*E_DIM, (size_t)SEQ*SEQ);

    softmax_k<<<NROWS, b256>>>(S_, Ph, Pl);

    // attn: P_b @ V_b  (B = Vt[E,S])
    mma_gemm<true, false><<<dim3(E_DIM/BN, SEQ/BM, NB), b256, SMEM_GEMM>>>(
        Ph, Pl, Vth, Vtl, nullptr, nullptr, ath, atl, E_DIM, SEQ,
        (size_t)SEQ*SEQ, (size_t)E_DIM*SEQ, (size_t)SEQ*E_DIM);

    // O projection
    mma_gemm<false,false><<<dim3(E_DIM/BN, NROWS/BM, 1), b256, SMEM_GEMM>>>(
        ath, atl, Woh, Wol, bo, tmp, nullptr, nullptr, E_DIM, E_DIM, 0, 0, 0);

    add_ln_k<true><<<NROWS, b256>>>(src, tmp, g1, be1, x, xh, xl);

    // FFN1 (relu, split out)
    mma_gemm<true, true><<<dim3(FF_DIM/BN, NROWS/BM, 1), b256, SMEM_GEMM>>>(
        xh, xl, W1h, W1l, b1, nullptr, ffh, ffl, FF_DIM, E_DIM, 0, 0, 0);

    // FFN2
    mma_gemm<false,false><<<dim3(E_DIM/BN, NROWS/BM, 1), b256, SMEM_GEMM>>>(
        ffh, ffl, W2h, W2l, b2, tmp, nullptr, nullptr, E_DIM, FF_DIM, 0, 0, 0);

    add_ln_k<false><<<NROWS, b256>>>(x, tmp, g2, be2, out, nullptr, nullptr);
}